// round 17
// baseline (speedup 1.0000x reference)
#include <cuda_runtime.h>
#include <cuda_fp16.h>
#include <stdint.h>
#include <math.h>

#define Bn 128
#define Ln 1024
#define Vn 32
#define En 256
#define Hn 1024
#define NTOT 1056        // Hn + Vn (W_o folded)

#define NG  4            // independent batch groups
#define BG  32           // batch rows per group
#define NTL 33           // CTAs per group (32 h-producers + 1 logits tile)
#define NSL 32           // N cols per CTA
#define G   (NG * NTL)   // 132 persistent CTAs
#define NT  256          // 8 warps (one per k-slice)
#define KW  128          // K columns per warp
#define PA  1032         // B smem pitch (fp16), setup only
#define PN  36           // reduction pitch (floats)

// ---------------- device scratch ----------------
__device__ float    g_P[Vn * Hn];
// h in MMA-fragment layout: [c][g][half][kf][ks][lane] as uint4 (a0..a3)
__device__ uint4    g_hfrag[3 * NG * 2 * 8 * 8 * 32];
__device__ __half   g_WT_hi[NTOT * Hn];     // [n][k] fp16 hi
__device__ __half   g_WT_lo[NTOT * Hn];     // fp16 residual
__device__ unsigned g_cnt_all;              // prologue barrier (all G)
__device__ unsigned g_flag[NG][32 * 8];     // per-producer half-step flags (32B padded)
__device__ unsigned g_flagL[NG * 8];        // logits-CTA read-done flags

#define FRAG_CSTride (NG * 2 * 8 * 8 * 32)  // uint4s per buffer

// smem layout (bytes): setup B staging uses [0, 132096)
#define OFF_BLO  66048                      // (setup only) B-lo staging
#define OFF_RED  66048                      // steady: sRed buf0 (36864 B)
#define OFF_RED1 102912                     // sRed buf1 (36864 B)
#define OFF_X    139776                     // sX[2][BG]
#define SMEM_BYTES 140032

// ---------------- helpers ----------------
#define MMAF16(d, a0, a1, a2, a3, b0, b1) \
    asm volatile("mma.sync.aligned.m16n8k16.row.col.f32.f16.f16.f32 " \
        "{%0,%1,%2,%3}, {%4,%5,%6,%7}, {%8,%9}, {%0,%1,%2,%3};" \
        : "+f"((d)[0]), "+f"((d)[1]), "+f"((d)[2]), "+f"((d)[3]) \
        : "r"(a0), "r"(a1), "r"(a2), "r"(a3), "r"(b0), "r"(b1))

#define LDSM4(r0, r1, r2, r3, addr) \
    asm volatile("ldmatrix.sync.aligned.m8n8.x4.shared.b16 {%0,%1,%2,%3}, [%4];" \
        : "=r"(r0), "=r"(r1), "=r"(r2), "=r"(r3) : "r"(addr))

__device__ __forceinline__ uint32_t smem_u32(const void* p) {
    uint32_t a;
    asm("{ .reg .u64 t; cvta.to.shared.u64 t, %1; cvt.u32.u64 %0, t; }"
        : "=r"(a) : "l"(p));
    return a;
}
__device__ __forceinline__ unsigned acqload(const unsigned* p) {
    unsigned v;
    asm volatile("ld.acquire.gpu.u32 %0, [%1];" : "=r"(v) : "l"(p) : "memory");
    return v;
}
__device__ __forceinline__ void relstore(unsigned* p, unsigned v) {
    asm volatile("st.release.gpu.u32 [%0], %1;" :: "l"(p), "r"(v) : "memory");
}
__device__ __forceinline__ void arrive(unsigned* cnt) {
    asm volatile("red.release.gpu.global.add.u32 [%0], 1;" :: "l"(cnt) : "memory");
}
__device__ __forceinline__ void waitcnt(unsigned* cnt, unsigned target) {
    unsigned v = acqload(cnt);
    while ((int)(v - target) < 0) v = acqload(cnt);
}
__device__ __forceinline__ uint4 ldcg4(const void* p) {
    uint4 r;
    asm volatile("ld.global.cg.v4.u32 {%0,%1,%2,%3}, [%4];"
        : "=r"(r.x), "=r"(r.y), "=r"(r.z), "=r"(r.w) : "l"(p));
    return r;
}
__device__ __forceinline__ void stcg32(void* p, uint32_t v) {
    asm volatile("st.global.cg.u32 [%0], %1;" :: "l"(p), "r"(v) : "memory");
}
__device__ __forceinline__ void pack_h16(float v, unsigned short& hi, unsigned short& lo) {
    __half hb = __float2half_rn(v);
    hi = __half_as_ushort(hb);
    lo = __half_as_ushort(__float2half_rn(v - __half2float(hb)));
}
__device__ __forceinline__ float fast_tanh(float x) {
    float e = __expf(2.0f * x);
    return 1.0f - __fdividef(2.0f, e + 1.0f);
}

// ---------------- the single persistent kernel ----------------
__global__ void __launch_bounds__(NT, 1)
rnn_all(const int* __restrict__ x, const float* __restrict__ hidden,
        const float* __restrict__ emb, const float* __restrict__ We,
        const float* __restrict__ Wh, const float* __restrict__ bh,
        const float* __restrict__ Wo, const float* __restrict__ bo,
        float* __restrict__ logits, float* __restrict__ outh) {
    extern __shared__ __align__(16) char dsm[];
    float* sRed0 = (float*)(dsm + OFF_RED);
    float* sRed1 = (float*)(dsm + OFF_RED1);
    int*   sX    = (int*)(dsm + OFF_X);

    const int tid = threadIdx.x, bid = blockIdx.x;
    const int g     = bid / NTL;
    const int ntl   = bid % NTL;
    const bool isProd = (ntl < NTL - 1);
    const int gbase = g * BG;
    const int ncol0 = ntl * NSL;
    const int lane = tid & 31, w = tid >> 5;
    const int gq = lane >> 2, tg = lane & 3;
    const int kw = w * KW;

    unsigned tokA = acqload(&g_cnt_all);
    unsigned fb = 0;
    if (lane < 4) fb = acqload(&g_flag[g][(w * 4 + lane) * 8]);
    unsigned fbSelf = 0;
    if (tid == 0 && isProd) fbSelf = acqload(&g_flag[g][ntl * 8]);
    const unsigned fbL = acqload(&g_flagL[g * 8]);

    const int rm  = tid >> 4;              // 0..15
    const int rn0 = (tid & 15) * 2;        // 0..30
    const int kg   = ncol0 + rn0;
    const int pkf  = kg >> 7;
    const int pks  = (kg >> 4) & 7;
    const int pcc  = kg & 15;
    const int plane = (rm & 7) * 4 + ((pcc & 7) >> 1);
    const int preg  = (rm >> 3) + 2 * (pcc >> 3);
    const int wOff0 = ((((g * 2 + 0) * 8 + pkf) * 8 + pks) * 32 + plane) * 4 + preg;
    const int wOff1 = ((((g * 2 + 1) * 8 + pkf) * 8 + pks) * 32 + plane) * 4 + preg;
    uint32_t* fragW = (uint32_t*)g_hfrag;

    const int cBase0 = (((g * 2 + 0) * 8 + w) * 8) * 32 + lane;
    const int cBase1 = (((g * 2 + 1) * 8 + w) * 8) * 32 + lane;

    // ======== prologue ========
    for (int k2 = tid; k2 < Hn; k2 += NT) {
#pragma unroll
        for (int j = 0; j < 8; ++j) {
            int n = bid * 8 + j;
            float wv = (n < Hn) ? Wh[k2 * Hn + n] : Wo[k2 * Vn + (n - Hn)];
            unsigned short hi, lo; pack_h16(wv, hi, lo);
            g_WT_hi[n * Hn + k2] = __ushort_as_half(hi);
            g_WT_lo[n * Hn + k2] = __ushort_as_half(lo);
        }
    }
    {
        int e = bid * NT + tid;
        if (e < Vn * Hn) {
            int v = e >> 10, h = e & 1023;
            float acc = bh[h];
            const float* er = emb + v * En;
#pragma unroll 8
            for (int q = 0; q < En; ++q) acc = fmaf(er[q], We[q * Hn + h], acc);
            g_P[e] = acc;
        }
    }
    if (isProd) {
#pragma unroll
        for (int hf = 0; hf < 2; ++hf) {
            int row = gbase + hf * 16 + rm;
            float v0 = hidden[row * Hn + kg];
            float v1 = hidden[row * Hn + kg + 1];
            unsigned short u0 = __half_as_ushort(__float2half_rn(v0));
            unsigned short u1 = __half_as_ushort(__float2half_rn(v1));
            fragW[(hf ? wOff1 : wOff0)] = (uint32_t)u0 | ((uint32_t)u1 << 16);
        }
    }
    __syncthreads();
    if (tid == 0) arrive(&g_cnt_all);
    tokA += G;
    if (tid == 0) waitcnt(&g_cnt_all, tokA);
    __syncthreads();

    // ======== B setup ========
    uint32_t Bh[8][4][2], Bl[8][4][2];
    {
        __half* sBhi = (__half*)dsm;
        __half* sBlo = (__half*)(dsm + OFF_BLO);
#pragma unroll
        for (int it = 0; it < 16; ++it) {
            int i = (it * NT + tid) * 8;
            int n = i >> 10, k = i & 1023;
            *(uint4*)(sBhi + n * PA + k) = *(const uint4*)(&g_WT_hi[(ncol0 + n) * Hn + k]);
            *(uint4*)(sBlo + n * PA + k) = *(const uint4*)(&g_WT_lo[(ncol0 + n) * Hn + k]);
        }
        __syncthreads();
        const uint32_t bBase = smem_u32(sBhi) +
            (uint32_t)(2 * ((lane & 7) * PA + kw + ((lane >> 3) & 1) * 8));
#pragma unroll
        for (int nb2 = 0; nb2 < 2; ++nb2) {
            const uint32_t ba = bBase + (uint32_t)(2 * (nb2 * 2 + (lane >> 4)) * 8 * PA);
#pragma unroll
            for (int ks = 0; ks < 8; ++ks) {
                LDSM4(Bh[ks][nb2 * 2][0], Bh[ks][nb2 * 2][1],
                      Bh[ks][nb2 * 2 + 1][0], Bh[ks][nb2 * 2 + 1][1], ba + ks * 32);
                LDSM4(Bl[ks][nb2 * 2][0], Bl[ks][nb2 * 2][1],
                      Bl[ks][nb2 * 2 + 1][0], Bl[ks][nb2 * 2 + 1][1],
                      ba + ks * 32 + (uint32_t)OFF_BLO);
            }
        }
        __syncthreads();
    }

    // ======== recurrence (2 syncs/step, deferred publishes) ========
    for (int l = 0; l <= Ln; ++l) {
        const int cRead  = l % 3;
        const int cWrite = (l + 1) % 3;
        const bool act = (l < Ln) || (!isProd);
        const uint4* frR = g_hfrag + cRead * FRAG_CSTride;
        uint32_t* frW = fragW + cWrite * (FRAG_CSTride * 4);
        int* sXb = sX + (l & 1) * BG;

        uint4 A[8];
        // ---- HALF 0: wait, load, MMA -> sRed0 ----
        if (act) {
            if (l > 0) {
                if (lane < 4) {
                    const unsigned* fp = &g_flag[g][(w * 4 + lane) * 8];
                    unsigned target = fb + (unsigned)(2 * l - 1);
                    while ((int)(acqload(fp) - target) < 0) {}
                }
                __syncwarp();
            }
#pragma unroll
            for (int ks = 0; ks < 8; ++ks)
                A[ks] = ldcg4(&frR[cBase0 + ks * 32]);
            if (l < Ln && tid < BG) sXb[tid] = __ldg(&x[(gbase + tid) * Ln + l]);

            float acc[4][4];
#pragma unroll
            for (int nb = 0; nb < 4; ++nb)
#pragma unroll
                for (int q = 0; q < 4; ++q) acc[nb][q] = 0.f;
#pragma unroll
            for (int ks = 0; ks < 8; ++ks)
#pragma unroll
                for (int nb = 0; nb < 4; ++nb) {
                    MMAF16(acc[nb], A[ks].x, A[ks].y, A[ks].z, A[ks].w,
                           Bh[ks][nb][0], Bh[ks][nb][1]);
                    MMAF16(acc[nb], A[ks].x, A[ks].y, A[ks].z, A[ks].w,
                           Bl[ks][nb][0], Bl[ks][nb][1]);
                }
            float* rp = sRed0 + w * 32 * PN;
#pragma unroll
            for (int nb = 0; nb < 4; ++nb) {
                int col = nb * 8 + tg * 2;
                *(float2*)(rp + gq * PN + col)       = make_float2(acc[nb][0], acc[nb][1]);
                *(float2*)(rp + (gq + 8) * PN + col) = make_float2(acc[nb][2], acc[nb][3]);
            }
        }
        __syncthreads();   // sync_a: half0 partials ready; prev-step h1 stores globally done

        // deferred publish: token 2l (h_l half1 complete), ordered by sync_a
        if (isProd && l >= 1 && tid == 0)
            relstore(&g_flag[g][ntl * 8], fbSelf + (unsigned)(2 * l));

        if (act) {
            // poll half1 flags early + issue A1 loads (overlap with reduce h0)
            if (l > 0) {
                if (lane < 4) {
                    const unsigned* fp = &g_flag[g][(w * 4 + lane) * 8];
                    unsigned target = fb + (unsigned)(2 * l);
                    while ((int)(acqload(fp) - target) < 0) {}
                }
                __syncwarp();
            }
#pragma unroll
            for (int ks = 0; ks < 8; ++ks)
                A[ks] = ldcg4(&frR[cBase1 + ks * 32]);

            // ---- reduce h0 + tanh + frag store (hides A1 LDG latency) ----
            {
                float2 s = *(const float2*)(sRed0 + rm * PN + rn0);
#pragma unroll
                for (int j = 1; j < 8; ++j) {
                    float2 p = *(const float2*)(sRed0 + j * 32 * PN + rm * PN + rn0);
                    s.x += p.x; s.y += p.y;
                }
                if (isProd) {
                    if (l < Ln) {
                        if (l > 1) {   // WAR: logits CTA done reading h_{l-2}
                            const unsigned* fp = &g_flagL[g * 8];
                            unsigned target = fbL + (unsigned)(l - 1);
                            while ((int)(acqload(fp) - target) < 0) {}
                        }
                        const int xv = sXb[rm];
                        float2 Pv = *(const float2*)(&g_P[xv * Hn + kg]);
                        float h0 = fast_tanh(s.x + Pv.x), h1 = fast_tanh(s.y + Pv.y);
                        unsigned short u0 = __half_as_ushort(__float2half_rn(h0));
                        unsigned short u1 = __half_as_ushort(__float2half_rn(h1));
                        stcg32(&frW[wOff0], (uint32_t)u0 | ((uint32_t)u1 << 16));
                        if (l == Ln - 1)
                            *(float2*)(&outh[(gbase + rm) * Hn + kg]) = make_float2(h0, h1);
                    }
                } else if (l > 0) {
                    float2 B0 = *(const float2*)(&bo[rn0]);
                    *(float2*)(&logits[((size_t)(gbase + rm) * Ln + (l - 1)) * Vn + rn0]) =
                        make_float2(s.x + B0.x, s.y + B0.y);
                }
            }

            // ---- HALF 1 MMA -> sRed1 ----
            float acc[4][4];
#pragma unroll
            for (int nb = 0; nb < 4; ++nb)
#pragma unroll
                for (int q = 0; q < 4; ++q) acc[nb][q] = 0.f;
#pragma unroll
            for (int ks = 0; ks < 8; ++ks)
#pragma unroll
                for (int nb = 0; nb < 4; ++nb) {
                    MMAF16(acc[nb], A[ks].x, A[ks].y, A[ks].z, A[ks].w,
                           Bh[ks][nb][0], Bh[ks][nb][1]);
                    MMAF16(acc[nb], A[ks].x, A[ks].y, A[ks].z, A[ks].w,
                           Bl[ks][nb][0], Bl[ks][nb][1]);
                }
            float* rp = sRed1 + w * 32 * PN;
#pragma unroll
            for (int nb = 0; nb < 4; ++nb) {
                int col = nb * 8 + tg * 2;
                *(float2*)(rp + gq * PN + col)       = make_float2(acc[nb][0], acc[nb][1]);
                *(float2*)(rp + (gq + 8) * PN + col) = make_float2(acc[nb][2], acc[nb][3]);
            }
        }
        __syncthreads();   // sync_c: half1 partials ready; h0 frag stores globally done

        // publish: token 2l+1 (h_{l+1} half0 complete), ordered by sync_c
        if (isProd && l < Ln && tid == 0)
            relstore(&g_flag[g][ntl * 8], fbSelf + (unsigned)(2 * l + 1));
        if (!isProd && tid == 0)
            relstore(&g_flagL[g * 8], fbL + (unsigned)(l + 1));

        if (act) {
            // ---- reduce h1 + tanh + frag store (publish deferred to next sync_a) ----
            const int m1 = 16 + rm;
            float2 s = *(const float2*)(sRed1 + rm * PN + rn0);
#pragma unroll
            for (int j = 1; j < 8; ++j) {
                float2 p = *(const float2*)(sRed1 + j * 32 * PN + rm * PN + rn0);
                s.x += p.x; s.y += p.y;
            }
            if (isProd) {
                if (l < Ln) {
                    const int xv = sXb[m1];
                    float2 Pv = *(const float2*)(&g_P[xv * Hn + kg]);
                    float h0 = fast_tanh(s.x + Pv.x), h1 = fast_tanh(s.y + Pv.y);
                    unsigned short u0 = __half_as_ushort(__float2half_rn(h0));
                    unsigned short u1 = __half_as_ushort(__float2half_rn(h1));
                    stcg32(&frW[wOff1], (uint32_t)u0 | ((uint32_t)u1 << 16));
                    if (l == Ln - 1)
                        *(float2*)(&outh[(gbase + m1) * Hn + kg]) = make_float2(h0, h1);
                }
            } else if (l > 0) {
                float2 B0 = *(const float2*)(&bo[rn0]);
                *(float2*)(&logits[((size_t)(gbase + m1) * Ln + (l - 1)) * Vn + rn0]) =
                    make_float2(s.x + B0.x, s.y + B0.y);
            }
        }
    }
}

extern "C" void kernel_launch(void* const* d_in, const int* in_sizes, int n_in,
                              void* d_out, int out_size) {
    const int*   x      = (const int*)d_in[0];
    const float* hidden = (const float*)d_in[1];
    const float* emb    = (const float*)d_in[2];
    const float* We     = (const float*)d_in[3];
    const float* Wh     = (const float*)d_in[4];
    const float* bh     = (const float*)d_in[5];
    const float* Wo     = (const float*)d_in[6];
    const float* bo     = (const float*)d_in[7];

    float* logits = (float*)d_out;
    float* outh   = logits + (size_t)Bn * Ln * Vn;

    cudaFuncSetAttribute(rnn_all,
                         cudaFuncAttributeMaxDynamicSharedMemorySize, SMEM_BYTES);
    rnn_all<<<G, NT, SMEM_BYTES>>>(x, hidden, emb, We, Wh, bh, Wo, bo, logits, outh);
}